// round 15
// baseline (speedup 1.0000x reference)
#include <cuda_runtime.h>
#include <cstdint>

// Problem constants (shapes fixed by dataset).
constexpr int Hdim   = 128;
constexpr int NLEAF  = 8192;
constexpr int NBATCH = 8;
constexpr int NL     = NBATCH * NLEAF;     // 65536 leaf edges
constexpr int NPT    = 24575;              // nodes per tree
constexpr int NN     = NBATCH * NPT;       // 196600 total nodes
constexpr int DEPTH  = 14;

constexpr int ASTR_BIG   = 260;            // smem stride for 256-wide inputs
constexpr int ASTR_SMALL = 132;            // smem stride for 128/129-wide

// big kernel smem:
//   modes 0/1: 64*260*4 (66560) + 2 x 32x128 chunks (32768) = 99328 -> 2 CTAs/SM
//   mode 2   : 64*132*4 (33792) + 2 x 32x128 chunks (32768) = 66560 -> 3 CTAs/SM
constexpr int SMEM_BIG_01 = (64 * ASTR_BIG)   * 4 + 2 * 32 * Hdim * 4;  // 99328
constexpr int SMEM_BIG_2  = (64 * ASTR_SMALL) * 4 + 2 * 32 * Hdim * 4;  // 66560
// small kernel smem (single-buffered scalar path)
constexpr int SMEM_SMALL  = (16 * ASTR_BIG + 64 * Hdim) * 4;            // 49408

// ---------------- packed fp32x2 helpers (Blackwell FFMA2) ----------------
typedef unsigned long long ull;

#define FMA_F32X2(d, a, b, c) \
    asm("fma.rn.f32x2 %0, %1, %2, %3;" : "=l"(d) : "l"(a), "l"(b), "l"(c))

#define PACK_DUP_F32X2(out, x) \
    asm("mov.b64 %0, {%1, %1};" : "=l"(out) : "r"(__float_as_uint(x)))

#define UNPACK_F32X2(lo, hi, v) \
    asm("mov.b64 {%0, %1}, %2;" : "=f"(lo), "=f"(hi) : "l"(v))

__device__ __forceinline__ void cp16(uint32_t dst, const void* src) {
    asm volatile("cp.async.cg.shared.global [%0], [%1], 16;" :: "r"(dst), "l"(src));
}

// ---- one MLP layer, cp.async double-buffered WCH-row weight chunks ----
// sW holds TWO WCHx128 chunks (ping-pong). 128 threads, RPT rows x 8 cols/thread.
template<int K, int ASTR, int RPT, int WCH>
__device__ __forceinline__ void layer_acc2(const float* __restrict__ sA,
                                           float* __restrict__ sW,
                                           const float* __restrict__ w,
                                           int tid, int r0, int c0,
                                           ull (&acc)[RPT][4])
{
    constexpr int NCH   = K / WCH;
    constexpr int NF4   = WCH * 32;            // float4s per chunk
    constexpr int CHB   = WCH * Hdim * 4;      // chunk bytes
    const uint32_t sWb = (uint32_t)__cvta_generic_to_shared(sW);

    // stage chunk 0 -> buf 0
    {
        const float4* src = reinterpret_cast<const float4*>(w);
#pragma unroll
        for (int idx = tid; idx < NF4; idx += 128)
            cp16(sWb + (uint32_t)idx * 16, src + idx);
        asm volatile("cp.async.commit_group;" ::: "memory");
    }
    int buf = 0;
#pragma unroll 1
    for (int ch = 0; ch < NCH; ++ch) {
        if (ch + 1 < NCH) {
            const float4* src =
                reinterpret_cast<const float4*>(w + (size_t)(ch + 1) * WCH * Hdim);
            uint32_t dst = sWb + (uint32_t)(buf ^ 1) * CHB;
#pragma unroll
            for (int idx = tid; idx < NF4; idx += 128)
                cp16(dst + (uint32_t)idx * 16, src + idx);
            asm volatile("cp.async.commit_group;" ::: "memory");
            asm volatile("cp.async.wait_group 1;" ::: "memory");
        } else {
            asm volatile("cp.async.wait_group 0;" ::: "memory");
        }
        __syncthreads();

        const float* sWc = sW + buf * (WCH * Hdim);
        const int k0 = ch * WCH;
#pragma unroll 2
        for (int kq = 0; kq < WCH / 4; ++kq) {
            float4 av[RPT];
#pragma unroll
            for (int i = 0; i < RPT; ++i)
                av[i] = *reinterpret_cast<const float4*>(sA + (r0 + i) * ASTR + k0 + kq * 4);
#pragma unroll
            for (int t = 0; t < 4; ++t) {
                const float* wr = sWc + (kq * 4 + t) * Hdim + c0;
                ulonglong2 wA = *reinterpret_cast<const ulonglong2*>(wr);
                ulonglong2 wB = *reinterpret_cast<const ulonglong2*>(wr + 4);
#pragma unroll
                for (int i = 0; i < RPT; ++i) {
                    float a = reinterpret_cast<const float*>(&av[i])[t];
                    ull aa; PACK_DUP_F32X2(aa, a);
                    FMA_F32X2(acc[i][0], aa, wA.x, acc[i][0]);
                    FMA_F32X2(acc[i][1], aa, wA.y, acc[i][1]);
                    FMA_F32X2(acc[i][2], aa, wB.x, acc[i][2]);
                    FMA_F32X2(acc[i][3], aa, wB.y, acc[i][3]);
                }
            }
        }
        __syncthreads();
        buf ^= 1;
    }
}

template<int RPT>
__device__ __forceinline__ void zero_acc2(ull (&acc)[RPT][4]) {
#pragma unroll
    for (int i = 0; i < RPT; ++i)
#pragma unroll
        for (int j = 0; j < 4; ++j) acc[i][j] = 0ull;
}

__device__ __forceinline__ void epi_bias_relu8(ull (&acc)[8][4],
                                               const float* __restrict__ b,
                                               float* __restrict__ sA,
                                               int r0, int c0)
{
    float4 bv0 = *reinterpret_cast<const float4*>(b + c0);
    float4 bv1 = *reinterpret_cast<const float4*>(b + c0 + 4);
    const float bv[8] = {bv0.x, bv0.y, bv0.z, bv0.w, bv1.x, bv1.y, bv1.z, bv1.w};
#pragma unroll
    for (int i = 0; i < 8; ++i) {
        float v[8];
#pragma unroll
        for (int jj = 0; jj < 4; ++jj) {
            float lo, hi; UNPACK_F32X2(lo, hi, acc[i][jj]);
            lo += bv[2 * jj];     hi += bv[2 * jj + 1];
            v[2 * jj]     = lo > 0.f ? lo : 0.f;
            v[2 * jj + 1] = hi > 0.f ? hi : 0.f;
        }
        *reinterpret_cast<float4*>(sA + (r0 + i) * ASTR_SMALL + c0) =
            make_float4(v[0], v[1], v[2], v[3]);
        *reinterpret_cast<float4*>(sA + (r0 + i) * ASTR_SMALL + c0 + 4) =
            make_float4(v[4], v[5], v[6], v[7]);
    }
}

// MODE 0: nem — in=[x[esrc[e]], ef[e]]               (K=256), out -> x[edst[e]]        (set)
// MODE 1: mg  — in=[x[esrc[s+r]], x[esrc[s+half+r]]] (K=256), out -> x[edst[s+half+r]] (set)
// MODE 2: mr  — in=[x[edst[e]], state[e]]            (K=129), out -> x[esrc[e]] += out
template<int MODE>
__global__ void __launch_bounds__(128, (MODE == 2) ? 3 : 2)
mlp_big(float* __restrict__ x,
        const float* __restrict__ ef,
        const int* __restrict__ esrc,
        const int* __restrict__ edst,
        const float* __restrict__ est,
        const float* __restrict__ w0, const float* __restrict__ b0,
        const float* __restrict__ w1, const float* __restrict__ b1,
        const float* __restrict__ w2, const float* __restrict__ b2,
        int s, int half, int nrows)
{
    constexpr int ASTR0 = (MODE == 2) ? ASTR_SMALL : ASTR_BIG;
    constexpr int WCH   = 32;
    extern __shared__ float sm[];
    float* sA = sm;
    float* sW = sm + 64 * ASTR0;

    const int tid = threadIdx.x;
    const int cx = tid & 15, ry = tid >> 4;      // 16 col-groups x 8 row-groups
    const int c0 = cx * 8, r0 = ry * 8;
    const int row_base = blockIdx.x * 64;

    // ---- gather inputs into sA ----
    if (MODE == 0 || MODE == 1) {
        for (int idx = tid; idx < 64 * 64; idx += 128) {
            int r = idx >> 6, c4 = idx & 63;
            int row = row_base + r;
            if (row < nrows) {
                float4 v;
                if (c4 < 32) {
                    int node = esrc[s + row];
                    v = reinterpret_cast<const float4*>(x + (size_t)node * Hdim)[c4];
                } else if (MODE == 0) {
                    v = reinterpret_cast<const float4*>(ef + (size_t)(s + row) * Hdim)[c4 - 32];
                } else {
                    int node = esrc[s + half + row];
                    v = reinterpret_cast<const float4*>(x + (size_t)node * Hdim)[c4 - 32];
                }
                reinterpret_cast<float4*>(sA + r * ASTR_BIG)[c4] = v;
            }
        }
    } else {
        for (int idx = tid; idx < 64 * 32; idx += 128) {
            int r = idx >> 5, c4 = idx & 31;
            int row = row_base + r;
            if (row < nrows) {
                int node = edst[s + row];
                float4 v = reinterpret_cast<const float4*>(x + (size_t)node * Hdim)[c4];
                reinterpret_cast<float4*>(sA + r * ASTR_SMALL)[c4] = v;
            }
        }
        for (int r = tid; r < 64; r += 128) {
            int row = row_base + r;
            sA[r * ASTR_SMALL + 128] = (row < nrows) ? est[s + row] : 0.f;
        }
    }
    __syncthreads();

    ull acc[8][4];

    // ---- layer 0 ----
    zero_acc2<8>(acc);
    if (MODE == 2) {
        layer_acc2<128, ASTR_SMALL, 8, WCH>(sA, sW, w0, tid, r0, c0, acc);
        const float* wsr = w0 + (size_t)128 * Hdim + c0;
        ulonglong2 wsA = *reinterpret_cast<const ulonglong2*>(wsr);
        ulonglong2 wsB = *reinterpret_cast<const ulonglong2*>(wsr + 4);
#pragma unroll
        for (int i = 0; i < 8; ++i) {
            float stv = sA[(r0 + i) * ASTR_SMALL + 128];
            ull aa; PACK_DUP_F32X2(aa, stv);
            FMA_F32X2(acc[i][0], aa, wsA.x, acc[i][0]);
            FMA_F32X2(acc[i][1], aa, wsA.y, acc[i][1]);
            FMA_F32X2(acc[i][2], aa, wsB.x, acc[i][2]);
            FMA_F32X2(acc[i][3], aa, wsB.y, acc[i][3]);
        }
    } else {
        layer_acc2<256, ASTR_BIG, 8, WCH>(sA, sW, w0, tid, r0, c0, acc);
    }
    epi_bias_relu8(acc, b0, sA, r0, c0);
    __syncthreads();

    // ---- layer 1 ----
    zero_acc2<8>(acc);
    layer_acc2<128, ASTR_SMALL, 8, WCH>(sA, sW, w1, tid, r0, c0, acc);
    epi_bias_relu8(acc, b1, sA, r0, c0);
    __syncthreads();

    // ---- layer 2 + scatter ----
    zero_acc2<8>(acc);
    layer_acc2<128, ASTR_SMALL, 8, WCH>(sA, sW, w2, tid, r0, c0, acc);
    {
        float4 bv0 = *reinterpret_cast<const float4*>(b2 + c0);
        float4 bv1 = *reinterpret_cast<const float4*>(b2 + c0 + 4);
        const float bv[8] = {bv0.x, bv0.y, bv0.z, bv0.w, bv1.x, bv1.y, bv1.z, bv1.w};
#pragma unroll
        for (int i = 0; i < 8; ++i) {
            int row = row_base + r0 + i;
            if (row >= nrows) continue;
            float v[8];
#pragma unroll
            for (int jj = 0; jj < 4; ++jj) {
                float lo, hi; UNPACK_F32X2(lo, hi, acc[i][jj]);
                v[2 * jj]     = lo + bv[2 * jj];
                v[2 * jj + 1] = hi + bv[2 * jj + 1];
            }

            int node;
            if (MODE == 0)      node = edst[s + row];
            else if (MODE == 1) node = edst[s + half + row];
            else                node = esrc[s + row];

            float* p = x + (size_t)node * Hdim + c0;
            if (MODE == 2) {
                float4 o0 = *reinterpret_cast<const float4*>(p);
                float4 o1 = *reinterpret_cast<const float4*>(p + 4);
                v[0] += o0.x; v[1] += o0.y; v[2] += o0.z; v[3] += o0.w;
                v[4] += o1.x; v[5] += o1.y; v[6] += o1.z; v[7] += o1.w;
            }
            *reinterpret_cast<float4*>(p)     = make_float4(v[0], v[1], v[2], v[3]);
            *reinterpret_cast<float4*>(p + 4) = make_float4(v[4], v[5], v[6], v[7]);
        }
    }
}

// =============== PAIRED MR kernel: 32 parents -> 64 output rows ============
// mr depth >= 2: edge rows p and half_m+p share the same parent; layer-0
// computed once per parent; rows expand as relu(z+b0) / relu(z+b0+w0_state).
// Bit-exact vs unpaired path. smem 66560 -> 3 CTAs/SM.
__global__ void __launch_bounds__(128, 3)
mlp_big_mr(float* __restrict__ x,
           const int* __restrict__ esrc,
           const int* __restrict__ edst,
           const float* __restrict__ w0, const float* __restrict__ b0,
           const float* __restrict__ w1, const float* __restrict__ b1,
           const float* __restrict__ w2, const float* __restrict__ b2,
           int s, int half_m)
{
    extern __shared__ float sm[];
    float* sA = sm;                              // 64 x ASTR_SMALL
    float* sW = sm + 64 * ASTR_SMALL;            // 2 x 32 x 128

    const int tid = threadIdx.x;
    const int cx = tid & 15, ry = tid >> 4;
    const int c0 = cx * 8;
    const int par_base = blockIdx.x * 32;

    // ---- gather 32 parent rows ----
    for (int idx = tid; idx < 32 * 32; idx += 128) {
        int r = idx >> 5, c4 = idx & 31;
        int p = par_base + r;
        if (p < half_m) {
            int node = edst[s + p];
            float4 v = reinterpret_cast<const float4*>(x + (size_t)node * Hdim)[c4];
            reinterpret_cast<float4*>(sA + r * ASTR_SMALL)[c4] = v;
        }
    }
    __syncthreads();

    // ---- layer 0: 32 rows, RPT=4 ----
    {
        ull acc4[4][4];
        zero_acc2<4>(acc4);
        const int r0p = ry * 4;
        layer_acc2<128, ASTR_SMALL, 4, 32>(sA, sW, w0, tid, r0p, c0, acc4);

        float4 bv0 = *reinterpret_cast<const float4*>(b0 + c0);
        float4 bv1 = *reinterpret_cast<const float4*>(b0 + c0 + 4);
        const float bv[8] = {bv0.x, bv0.y, bv0.z, bv0.w, bv1.x, bv1.y, bv1.z, bv1.w};
        const float* wsr = w0 + (size_t)128 * Hdim + c0;
        float4 wsa = *reinterpret_cast<const float4*>(wsr);
        float4 wsb = *reinterpret_cast<const float4*>(wsr + 4);
        const float ws[8] = {wsa.x, wsa.y, wsa.z, wsa.w, wsb.x, wsb.y, wsb.z, wsb.w};

#pragma unroll
        for (int i = 0; i < 4; ++i) {
            int p = r0p + i;
            float z[8], l[8], rr[8];
#pragma unroll
            for (int jj = 0; jj < 4; ++jj) {
                float lo, hi; UNPACK_F32X2(lo, hi, acc4[i][jj]);
                z[2 * jj]     = lo + bv[2 * jj];
                z[2 * jj + 1] = hi + bv[2 * jj + 1];
            }
#pragma unroll
            for (int j = 0; j < 8; ++j) {
                float lv = z[j];
                float rv = z[j] + ws[j];
                l[j]  = lv > 0.f ? lv : 0.f;
                rr[j] = rv > 0.f ? rv : 0.f;
            }
            *reinterpret_cast<float4*>(sA + p * ASTR_SMALL + c0) =
                make_float4(l[0], l[1], l[2], l[3]);
            *reinterpret_cast<float4*>(sA + p * ASTR_SMALL + c0 + 4) =
                make_float4(l[4], l[5], l[6], l[7]);
            *reinterpret_cast<float4*>(sA + (32 + p) * ASTR_SMALL + c0) =
                make_float4(rr[0], rr[1], rr[2], rr[3]);
            *reinterpret_cast<float4*>(sA + (32 + p) * ASTR_SMALL + c0 + 4) =
                make_float4(rr[4], rr[5], rr[6], rr[7]);
        }
    }
    __syncthreads();

    const int r0 = ry * 8;
    ull acc[8][4];

    // ---- layer 1 (64 rows) ----
    zero_acc2<8>(acc);
    layer_acc2<128, ASTR_SMALL, 8, 32>(sA, sW, w1, tid, r0, c0, acc);
    epi_bias_relu8(acc, b1, sA, r0, c0);
    __syncthreads();

    // ---- layer 2 + scatter (64 rows) ----
    zero_acc2<8>(acc);
    layer_acc2<128, ASTR_SMALL, 8, 32>(sA, sW, w2, tid, r0, c0, acc);
    {
        float4 bv0 = *reinterpret_cast<const float4*>(b2 + c0);
        float4 bv1 = *reinterpret_cast<const float4*>(b2 + c0 + 4);
        const float bv[8] = {bv0.x, bv0.y, bv0.z, bv0.w, bv1.x, bv1.y, bv1.z, bv1.w};
#pragma unroll
        for (int i = 0; i < 8; ++i) {
            int li = r0 + i;
            int lp = (li < 32) ? li : (li - 32);
            int p  = par_base + lp;
            if (p >= half_m) continue;
            int erow = (li < 32) ? p : (half_m + p);

            float v[8];
#pragma unroll
            for (int jj = 0; jj < 4; ++jj) {
                float lo, hi; UNPACK_F32X2(lo, hi, acc[i][jj]);
                v[2 * jj]     = lo + bv[2 * jj];
                v[2 * jj + 1] = hi + bv[2 * jj + 1];
            }

            int node = esrc[s + erow];
            float* pp = x + (size_t)node * Hdim + c0;
            float4 o0 = *reinterpret_cast<const float4*>(pp);
            float4 o1 = *reinterpret_cast<const float4*>(pp + 4);
            v[0] += o0.x; v[1] += o0.y; v[2] += o0.z; v[3] += o0.w;
            v[4] += o1.x; v[5] += o1.y; v[6] += o1.z; v[7] += o1.w;
            *reinterpret_cast<float4*>(pp)     = make_float4(v[0], v[1], v[2], v[3]);
            *reinterpret_cast<float4*>(pp + 4) = make_float4(v[4], v[5], v[6], v[7]);
        }
    }
}

// =============== SMALL kernel: 16-row tiles, 256 threads, 1x8/thread =======

template<int K, int ASTR>
__device__ __forceinline__ void layer_acc_s(const float* __restrict__ sA,
                                            float* __restrict__ sW,
                                            const float* __restrict__ w,
                                            int tid, int r0, int c0,
                                            float (&acc)[8])
{
#pragma unroll 1
    for (int k0 = 0; k0 < K; k0 += 64) {
        for (int idx = tid; idx < 64 * 32; idx += 256) {
            reinterpret_cast<float4*>(sW)[idx] =
                reinterpret_cast<const float4*>(w + (size_t)k0 * Hdim)[idx];
        }
        __syncthreads();
#pragma unroll 4
        for (int kq = 0; kq < 16; ++kq) {
            float4 av = *reinterpret_cast<const float4*>(sA + r0 * ASTR + k0 + kq * 4);
#pragma unroll
            for (int t = 0; t < 4; ++t) {
                const float* wr = sW + (kq * 4 + t) * Hdim + c0;
                float4 w0v = *reinterpret_cast<const float4*>(wr);
                float4 w1v = *reinterpret_cast<const float4*>(wr + 4);
                float a = reinterpret_cast<const float*>(&av)[t];
                acc[0] = fmaf(a, w0v.x, acc[0]);
                acc[1] = fmaf(a, w0v.y, acc[1]);
                acc[2] = fmaf(a, w0v.z, acc[2]);
                acc[3] = fmaf(a, w0v.w, acc[3]);
                acc[4] = fmaf(a, w1v.x, acc[4]);
                acc[5] = fmaf(a, w1v.y, acc[5]);
                acc[6] = fmaf(a, w1v.z, acc[6]);
                acc[7] = fmaf(a, w1v.w, acc[7]);
            }
        }
        __syncthreads();
    }
}

template<int MODE>
__global__ void __launch_bounds__(256)
mlp_small(float* __restrict__ x,
          const float* __restrict__ ef,
          const int* __restrict__ esrc,
          const int* __restrict__ edst,
          const float* __restrict__ est,
          const float* __restrict__ w0, const float* __restrict__ b0,
          const float* __restrict__ w1, const float* __restrict__ b1,
          const float* __restrict__ w2, const float* __restrict__ b2,
          int s, int half, int nrows)
{
    extern __shared__ float sm[];
    float* sA = sm;
    float* sW = sm + 16 * ASTR_BIG;

    const int tid = threadIdx.x;
    const int cx = tid & 15, ry = tid >> 4;
    const int c0 = cx * 8, r0 = ry;
    const int row_base = blockIdx.x * 16;

    if (MODE == 0 || MODE == 1) {
        for (int idx = tid; idx < 16 * 64; idx += 256) {
            int r = idx >> 6, c4 = idx & 63;
            int row = row_base + r;
            if (row < nrows) {
                float4 v;
                if (c4 < 32) {
                    int node = esrc[s + row];
                    v = reinterpret_cast<const float4*>(x + (size_t)node * Hdim)[c4];
                } else if (MODE == 0) {
                    v = reinterpret_cast<const float4*>(ef + (size_t)(s + row) * Hdim)[c4 - 32];
                } else {
                    int node = esrc[s + half + row];
                    v = reinterpret_cast<const float4*>(x + (size_t)node * Hdim)[c4 - 32];
                }
                reinterpret_cast<float4*>(sA + r * ASTR_BIG)[c4] = v;
            }
        }
    } else {
        for (int idx = tid; idx < 16 * 32; idx += 256) {
            int r = idx >> 5, c4 = idx & 31;
            int row = row_base + r;
            if (row < nrows) {
                int node = edst[s + row];
                float4 v = reinterpret_cast<const float4*>(x + (size_t)node * Hdim)[c4];
                reinterpret_cast<float4*>(sA + r * ASTR_SMALL)[c4] = v;
            }
        }
        for (int r = tid; r < 16; r += 256) {
            int row = row_base + r;
            sA[r * ASTR_SMALL + 128] = (row < nrows) ? est[s + row] : 0.f;
        }
    }
    __syncthreads();

    float acc[8];

#pragma unroll
    for (int j = 0; j < 8; ++j) acc[j] = 0.f;
    if (MODE == 2) {
        layer_acc_s<128, ASTR_SMALL>(sA, sW, w0, tid, r0, c0, acc);
        const float* wsr = w0 + (size_t)128 * Hdim + c0;
        float stv = sA[r0 * ASTR_SMALL + 128];
#pragma unroll
        for (int j = 0; j < 8; ++j) acc[j] = fmaf(stv, wsr[j], acc[j]);
    } else {
        layer_acc_s<256, ASTR_BIG>(sA, sW, w0, tid, r0, c0, acc);
    }
    {
#pragma unroll
        for (int j = 0; j < 8; ++j) {
            float v = acc[j] + b0[c0 + j];
            acc[j] = v > 0.f ? v : 0.f;
        }
        *reinterpret_cast<float4*>(sA + r0 * ASTR_SMALL + c0) =
            make_float4(acc[0], acc[1], acc[2], acc[3]);
        *reinterpret_cast<float4*>(sA + r0 * ASTR_SMALL + c0 + 4) =
            make_float4(acc[4], acc[5], acc[6], acc[7]);
    }
    __syncthreads();

#pragma unroll
    for (int j = 0; j < 8; ++j) acc[j] = 0.f;
    layer_acc_s<128, ASTR_SMALL>(sA, sW, w1, tid, r0, c0, acc);
    {
#pragma unroll
        for (int j = 0; j < 8; ++j) {
            float v = acc[j] + b1[c0 + j];
            acc[j] = v > 0.f ? v : 0.f;
        }
        *reinterpret_cast<float4*>(sA + r0 * ASTR_SMALL + c0) =
            make_float4(acc[0], acc[1], acc[2], acc[3]);
        *reinterpret_cast<float4*>(sA + r0 * ASTR_SMALL + c0 + 4) =
            make_float4(acc[4], acc[5], acc[6], acc[7]);
    }
    __syncthreads();

#pragma unroll
    for (int j = 0; j < 8; ++j) acc[j] = 0.f;
    layer_acc_s<128, ASTR_SMALL>(sA, sW, w2, tid, r0, c0, acc);
    {
        int row = row_base + r0;
        if (row < nrows) {
#pragma unroll
            for (int j = 0; j < 8; ++j) acc[j] += b2[c0 + j];

            int node;
            if (MODE == 0)      node = edst[s + row];
            else if (MODE == 1) node = edst[s + half + row];
            else                node = esrc[s + row];

            float* p = x + (size_t)node * Hdim + c0;
            if (MODE == 2) {
                float4 o0 = *reinterpret_cast<const float4*>(p);
                float4 o1 = *reinterpret_cast<const float4*>(p + 4);
                acc[0] += o0.x; acc[1] += o0.y; acc[2] += o0.z; acc[3] += o0.w;
                acc[4] += o1.x; acc[5] += o1.y; acc[6] += o1.z; acc[7] += o1.w;
            }
            *reinterpret_cast<float4*>(p)     = make_float4(acc[0], acc[1], acc[2], acc[3]);
            *reinterpret_cast<float4*>(p + 4) = make_float4(acc[4], acc[5], acc[6], acc[7]);
        }
    }
}

// copy only leaf rows of x (everything else is provably overwritten)
__global__ void leaf_copy_kernel(float* __restrict__ x, const float* __restrict__ x_in)
{
    int idx = blockIdx.x * blockDim.x + threadIdx.x;   // over NL*32 float4s
    if (idx >= NL * 32) return;
    int r = idx >> 5, c4 = idx & 31;
    int b = r >> 13, leaf = r & (NLEAF - 1);
    size_t node = (size_t)b * NPT + leaf;
    reinterpret_cast<float4*>(x + node * Hdim)[c4] =
        reinterpret_cast<const float4*>(x_in + node * Hdim)[c4];
}

extern "C" void kernel_launch(void* const* d_in, const int* in_sizes, int n_in,
                              void* d_out, int out_size)
{
    (void)n_in; (void)out_size;

    const float* x_in = (const float*)d_in[0];
    const int*   esrc = (const int*)  d_in[1];
    const int*   edst = (const int*)  d_in[2];
    const float* est  = (const float*)d_in[3];
    const float* ef   = (const float*)d_in[4];

    int wb = (in_sizes[5] == 1) ? 6 : 5;   // input 5 = scalar gcmn_depth

    const float* nem_w0 = (const float*)d_in[wb + 0];
    const float* nem_b0 = (const float*)d_in[wb + 1];
    const float* nem_w1 = (const float*)d_in[wb + 2];
    const float* nem_b1 = (const float*)d_in[wb + 3];
    const float* nem_w2 = (const float*)d_in[wb + 4];
    const float* nem_b2 = (const float*)d_in[wb + 5];
    const float* mg_w0  = (const float*)d_in[wb + 6];
    const float* mg_b0  = (const float*)d_in[wb + 7];
    const float* mg_w1  = (const float*)d_in[wb + 8];
    const float* mg_b1  = (const float*)d_in[wb + 9];
    const float* mg_w2  = (const float*)d_in[wb + 10];
    const float* mg_b2  = (const float*)d_in[wb + 11];
    const float* mr_w0  = (const float*)d_in[wb + 12];
    const float* mr_b0  = (const float*)d_in[wb + 13];
    const float* mr_w1  = (const float*)d_in[wb + 14];
    const float* mr_b1  = (const float*)d_in[wb + 15];
    const float* mr_w2  = (const float*)d_in[wb + 16];
    const float* mr_b2  = (const float*)d_in[wb + 17];

    float* x = (float*)d_out;

    cudaFuncSetAttribute(mlp_big<0>,  cudaFuncAttributeMaxDynamicSharedMemorySize, SMEM_BIG_01);
    cudaFuncSetAttribute(mlp_big<1>,  cudaFuncAttributeMaxDynamicSharedMemorySize, SMEM_BIG_01);
    cudaFuncSetAttribute(mlp_big<2>,  cudaFuncAttributeMaxDynamicSharedMemorySize, SMEM_BIG_2);
    cudaFuncSetAttribute(mlp_big_mr,  cudaFuncAttributeMaxDynamicSharedMemorySize, SMEM_BIG_2);
    cudaFuncSetAttribute(mlp_small<1>, cudaFuncAttributeMaxDynamicSharedMemorySize, SMEM_SMALL);
    cudaFuncSetAttribute(mlp_small<2>, cudaFuncAttributeMaxDynamicSharedMemorySize, SMEM_SMALL);

    // init: only leaf rows need the original x
    leaf_copy_kernel<<<(NL * 32 + 255) / 256, 256>>>(x, x_in);

    // edge-block layout: block 0 = leaf edges (NL), block d (1..13): 8*(NLEAF>>(d-1)) edges
    int cnt[14], st[14];
    cnt[0] = NL; st[0] = 0;
    for (int d = 1; d < DEPTH; ++d) {
        cnt[d] = 8 * (NLEAF >> (d - 1));
        st[d] = st[d - 1] + cnt[d - 1];
    }

    constexpr int SMALL_THRESH = 2048;

    // ---- nem: leaf -> level-1 ----
    mlp_big<0><<<NL / 64, 128, SMEM_BIG_01>>>(
        x, ef, esrc, edst, nullptr,
        nem_w0, nem_b0, nem_w1, nem_b1, nem_w2, nem_b2, 0, 0, NL);

    // ---- mg: upward merge, levels 1..13 (sequential) ----
    for (int d = 1; d < DEPTH; ++d) {
        int half = cnt[d] / 2;
        if (half <= SMALL_THRESH)
            mlp_small<1><<<(half + 15) / 16, 256, SMEM_SMALL>>>(
                x, nullptr, esrc, edst, nullptr,
                mg_w0, mg_b0, mg_w1, mg_b1, mg_w2, mg_b2, st[d], half, half);
        else
            mlp_big<1><<<(half + 63) / 64, 128, SMEM_BIG_01>>>(
                x, nullptr, esrc, edst, nullptr,
                mg_w0, mg_b0, mg_w1, mg_b1, mg_w2, mg_b2, st[d], half, half);
    }

    // ---- mr: downward, depth 14..1 (sequential) ----
    for (int depth = DEPTH; depth >= 1; --depth) {
        if (depth == 1) {
            // leaf edges: unpaired (unique dst, state 0), full 65536 rows
            mlp_big<2><<<(NL + 63) / 64, 128, SMEM_BIG_2>>>(
                x, nullptr, esrc, edst, est,
                mr_w0, mr_b0, mr_w1, mr_b1, mr_w2, mr_b2, 0, 0, NL);
        } else {
            int b = depth - 1;
            int sE = st[b], m = cnt[b];
            if (m <= SMALL_THRESH)
                mlp_small<2><<<(m + 15) / 16, 256, SMEM_SMALL>>>(
                    x, nullptr, esrc, edst, est,
                    mr_w0, mr_b0, mr_w1, mr_b1, mr_w2, mr_b2, sE, 0, m);
            else {
                int half_m = m / 2;
                mlp_big_mr<<<(half_m + 31) / 32, 128, SMEM_BIG_2>>>(
                    x, esrc, edst,
                    mr_w0, mr_b0, mr_w1, mr_b1, mr_w2, mr_b2, sE, half_m);
            }
        }
    }
}

// round 16
// speedup vs baseline: 1.0669x; 1.0669x over previous
#include <cuda_runtime.h>
#include <cstdint>

// Problem constants (shapes fixed by dataset).
constexpr int Hdim   = 128;
constexpr int NLEAF  = 8192;
constexpr int NBATCH = 8;
constexpr int NL     = NBATCH * NLEAF;     // 65536 leaf edges
constexpr int NPT    = 24575;              // nodes per tree
constexpr int NN     = NBATCH * NPT;       // 196600 total nodes
constexpr int DEPTH  = 14;

constexpr int ASTR_BIG   = 260;            // smem stride for 256-wide inputs
constexpr int ASTR_SMALL = 132;            // smem stride for 128/129-wide

// big kernel smem — both exactly 99328 B so 2 CTAs/SM fit (198KB < 228KB):
//   modes 0/1: 64*260*4 (66560) + 2 x 32x128 weight chunks (32768)
//   mode 2   : 64*132*4 (33792) + 2 x 64x128 weight chunks (65536)
constexpr int SMEM_BIG_01 = (64 * ASTR_BIG)   * 4 + 2 * 32 * Hdim * 4;  // 99328
constexpr int SMEM_BIG_2  = (64 * ASTR_SMALL) * 4 + 2 * 64 * Hdim * 4;  // 99328
// small kernel smem: 16*260*4 (16640) + 2 x 32x128 chunks (32768) = 49408 (same as before)
constexpr int SMEM_SMALL  = (16 * ASTR_BIG) * 4 + 2 * 32 * Hdim * 4;    // 49408

// ---------------- packed fp32x2 helpers (Blackwell FFMA2) ----------------
typedef unsigned long long ull;

#define FMA_F32X2(d, a, b, c) \
    asm("fma.rn.f32x2 %0, %1, %2, %3;" : "=l"(d) : "l"(a), "l"(b), "l"(c))

#define PACK_DUP_F32X2(out, x) \
    asm("mov.b64 %0, {%1, %1};" : "=l"(out) : "r"(__float_as_uint(x)))

#define UNPACK_F32X2(lo, hi, v) \
    asm("mov.b64 {%0, %1}, %2;" : "=f"(lo), "=f"(hi) : "l"(v))

__device__ __forceinline__ void cp16(uint32_t dst, const void* src) {
    asm volatile("cp.async.cg.shared.global [%0], [%1], 16;" :: "r"(dst), "l"(src));
}

// ---- one MLP layer, cp.async double-buffered WCH-row weight chunks ----
// sW holds TWO WCHx128 chunks (ping-pong). 128 threads, RPT rows x 8 cols/thread.
template<int K, int ASTR, int RPT, int WCH>
__device__ __forceinline__ void layer_acc2(const float* __restrict__ sA,
                                           float* __restrict__ sW,
                                           const float* __restrict__ w,
                                           int tid, int r0, int c0,
                                           ull (&acc)[RPT][4])
{
    constexpr int NCH   = K / WCH;
    constexpr int NF4   = WCH * 32;            // float4s per chunk
    constexpr int CHB   = WCH * Hdim * 4;      // chunk bytes
    const uint32_t sWb = (uint32_t)__cvta_generic_to_shared(sW);

    // stage chunk 0 -> buf 0
    {
        const float4* src = reinterpret_cast<const float4*>(w);
#pragma unroll
        for (int idx = tid; idx < NF4; idx += 128)
            cp16(sWb + (uint32_t)idx * 16, src + idx);
        asm volatile("cp.async.commit_group;" ::: "memory");
    }
    int buf = 0;
#pragma unroll 1
    for (int ch = 0; ch < NCH; ++ch) {
        if (ch + 1 < NCH) {
            const float4* src =
                reinterpret_cast<const float4*>(w + (size_t)(ch + 1) * WCH * Hdim);
            uint32_t dst = sWb + (uint32_t)(buf ^ 1) * CHB;
#pragma unroll
            for (int idx = tid; idx < NF4; idx += 128)
                cp16(dst + (uint32_t)idx * 16, src + idx);
            asm volatile("cp.async.commit_group;" ::: "memory");
            asm volatile("cp.async.wait_group 1;" ::: "memory");
        } else {
            asm volatile("cp.async.wait_group 0;" ::: "memory");
        }
        __syncthreads();

        const float* sWc = sW + buf * (WCH * Hdim);
        const int k0 = ch * WCH;
#pragma unroll 2
        for (int kq = 0; kq < WCH / 4; ++kq) {
            float4 av[RPT];
#pragma unroll
            for (int i = 0; i < RPT; ++i)
                av[i] = *reinterpret_cast<const float4*>(sA + (r0 + i) * ASTR + k0 + kq * 4);
#pragma unroll
            for (int t = 0; t < 4; ++t) {
                const float* wr = sWc + (kq * 4 + t) * Hdim + c0;
                ulonglong2 wA = *reinterpret_cast<const ulonglong2*>(wr);
                ulonglong2 wB = *reinterpret_cast<const ulonglong2*>(wr + 4);
#pragma unroll
                for (int i = 0; i < RPT; ++i) {
                    float a = reinterpret_cast<const float*>(&av[i])[t];
                    ull aa; PACK_DUP_F32X2(aa, a);
                    FMA_F32X2(acc[i][0], aa, wA.x, acc[i][0]);
                    FMA_F32X2(acc[i][1], aa, wA.y, acc[i][1]);
                    FMA_F32X2(acc[i][2], aa, wB.x, acc[i][2]);
                    FMA_F32X2(acc[i][3], aa, wB.y, acc[i][3]);
                }
            }
        }
        __syncthreads();
        buf ^= 1;
    }
}

template<int RPT>
__device__ __forceinline__ void zero_acc2(ull (&acc)[RPT][4]) {
#pragma unroll
    for (int i = 0; i < RPT; ++i)
#pragma unroll
        for (int j = 0; j < 4; ++j) acc[i][j] = 0ull;
}

__device__ __forceinline__ void epi_bias_relu8(ull (&acc)[8][4],
                                               const float* __restrict__ b,
                                               float* __restrict__ sA,
                                               int r0, int c0)
{
    float4 bv0 = *reinterpret_cast<const float4*>(b + c0);
    float4 bv1 = *reinterpret_cast<const float4*>(b + c0 + 4);
    const float bv[8] = {bv0.x, bv0.y, bv0.z, bv0.w, bv1.x, bv1.y, bv1.z, bv1.w};
#pragma unroll
    for (int i = 0; i < 8; ++i) {
        float v[8];
#pragma unroll
        for (int jj = 0; jj < 4; ++jj) {
            float lo, hi; UNPACK_F32X2(lo, hi, acc[i][jj]);
            lo += bv[2 * jj];     hi += bv[2 * jj + 1];
            v[2 * jj]     = lo > 0.f ? lo : 0.f;
            v[2 * jj + 1] = hi > 0.f ? hi : 0.f;
        }
        *reinterpret_cast<float4*>(sA + (r0 + i) * ASTR_SMALL + c0) =
            make_float4(v[0], v[1], v[2], v[3]);
        *reinterpret_cast<float4*>(sA + (r0 + i) * ASTR_SMALL + c0 + 4) =
            make_float4(v[4], v[5], v[6], v[7]);
    }
}

// MODE 0: nem — in=[x[esrc[e]], ef[e]]               (K=256), out -> x[edst[e]]        (set)
// MODE 1: mg  — in=[x[esrc[s+r]], x[esrc[s+half+r]]] (K=256), out -> x[edst[s+half+r]] (set)
// MODE 2: mr  — in=[x[edst[e]], state[e]]            (K=129), out -> x[esrc[e]] += out
template<int MODE>
__global__ void __launch_bounds__(128)
mlp_big(float* __restrict__ x,
        const float* __restrict__ ef,
        const int* __restrict__ esrc,
        const int* __restrict__ edst,
        const float* __restrict__ est,
        const float* __restrict__ w0, const float* __restrict__ b0,
        const float* __restrict__ w1, const float* __restrict__ b1,
        const float* __restrict__ w2, const float* __restrict__ b2,
        int s, int half, int nrows)
{
    constexpr int ASTR0 = (MODE == 2) ? ASTR_SMALL : ASTR_BIG;
    constexpr int WCH   = (MODE == 2) ? 64 : 32;   // keep smem at 99328 B
    extern __shared__ float sm[];
    float* sA = sm;
    float* sW = sm + 64 * ASTR0;

    const int tid = threadIdx.x;
    const int cx = tid & 15, ry = tid >> 4;      // 16 col-groups x 8 row-groups
    const int c0 = cx * 8, r0 = ry * 8;
    const int row_base = blockIdx.x * 64;

    // ---- gather inputs into sA ----
    if (MODE == 0 || MODE == 1) {
        for (int idx = tid; idx < 64 * 64; idx += 128) {
            int r = idx >> 6, c4 = idx & 63;
            int row = row_base + r;
            if (row < nrows) {
                float4 v;
                if (c4 < 32) {
                    int node = esrc[s + row];
                    v = reinterpret_cast<const float4*>(x + (size_t)node * Hdim)[c4];
                } else if (MODE == 0) {
                    v = reinterpret_cast<const float4*>(ef + (size_t)(s + row) * Hdim)[c4 - 32];
                } else {
                    int node = esrc[s + half + row];
                    v = reinterpret_cast<const float4*>(x + (size_t)node * Hdim)[c4 - 32];
                }
                reinterpret_cast<float4*>(sA + r * ASTR_BIG)[c4] = v;
            }
        }
    } else {
        for (int idx = tid; idx < 64 * 32; idx += 128) {
            int r = idx >> 5, c4 = idx & 31;
            int row = row_base + r;
            if (row < nrows) {
                int node = edst[s + row];
                float4 v = reinterpret_cast<const float4*>(x + (size_t)node * Hdim)[c4];
                reinterpret_cast<float4*>(sA + r * ASTR_SMALL)[c4] = v;
            }
        }
        for (int r = tid; r < 64; r += 128) {
            int row = row_base + r;
            sA[r * ASTR_SMALL + 128] = (row < nrows) ? est[s + row] : 0.f;
        }
    }
    __syncthreads();

    ull acc[8][4];

    // ---- layer 0 ----
    zero_acc2<8>(acc);
    if (MODE == 2) {
        layer_acc2<128, ASTR_SMALL, 8, WCH>(sA, sW, w0, tid, r0, c0, acc);
        const float* wsr = w0 + (size_t)128 * Hdim + c0;
        ulonglong2 wsA = *reinterpret_cast<const ulonglong2*>(wsr);
        ulonglong2 wsB = *reinterpret_cast<const ulonglong2*>(wsr + 4);
#pragma unroll
        for (int i = 0; i < 8; ++i) {
            float stv = sA[(r0 + i) * ASTR_SMALL + 128];
            ull aa; PACK_DUP_F32X2(aa, stv);
            FMA_F32X2(acc[i][0], aa, wsA.x, acc[i][0]);
            FMA_F32X2(acc[i][1], aa, wsA.y, acc[i][1]);
            FMA_F32X2(acc[i][2], aa, wsB.x, acc[i][2]);
            FMA_F32X2(acc[i][3], aa, wsB.y, acc[i][3]);
        }
    } else {
        layer_acc2<256, ASTR_BIG, 8, WCH>(sA, sW, w0, tid, r0, c0, acc);
    }
    epi_bias_relu8(acc, b0, sA, r0, c0);
    __syncthreads();

    // ---- layer 1 ----
    zero_acc2<8>(acc);
    layer_acc2<128, ASTR_SMALL, 8, WCH>(sA, sW, w1, tid, r0, c0, acc);
    epi_bias_relu8(acc, b1, sA, r0, c0);
    __syncthreads();

    // ---- layer 2 + scatter ----
    zero_acc2<8>(acc);
    layer_acc2<128, ASTR_SMALL, 8, WCH>(sA, sW, w2, tid, r0, c0, acc);
    {
        float4 bv0 = *reinterpret_cast<const float4*>(b2 + c0);
        float4 bv1 = *reinterpret_cast<const float4*>(b2 + c0 + 4);
        const float bv[8] = {bv0.x, bv0.y, bv0.z, bv0.w, bv1.x, bv1.y, bv1.z, bv1.w};
#pragma unroll
        for (int i = 0; i < 8; ++i) {
            int row = row_base + r0 + i;
            if (row >= nrows) continue;
            float v[8];
#pragma unroll
            for (int jj = 0; jj < 4; ++jj) {
                float lo, hi; UNPACK_F32X2(lo, hi, acc[i][jj]);
                v[2 * jj]     = lo + bv[2 * jj];
                v[2 * jj + 1] = hi + bv[2 * jj + 1];
            }

            int node;
            if (MODE == 0)      node = edst[s + row];
            else if (MODE == 1) node = edst[s + half + row];
            else                node = esrc[s + row];

            float* p = x + (size_t)node * Hdim + c0;
            if (MODE == 2) {
                float4 o0 = *reinterpret_cast<const float4*>(p);
                float4 o1 = *reinterpret_cast<const float4*>(p + 4);
                v[0] += o0.x; v[1] += o0.y; v[2] += o0.z; v[3] += o0.w;
                v[4] += o1.x; v[5] += o1.y; v[6] += o1.z; v[7] += o1.w;
            }
            *reinterpret_cast<float4*>(p)     = make_float4(v[0], v[1], v[2], v[3]);
            *reinterpret_cast<float4*>(p + 4) = make_float4(v[4], v[5], v[6], v[7]);
        }
    }
}

// =============== PAIRED MR kernel: 32 parents -> 64 output rows ============
// mr depth >= 2: edge rows p and half_m+p share the same parent; layer-0
// computed once per parent; rows expand as relu(z+b0) / relu(z+b0+w0_state).
// Bit-exact vs unpaired path.
__global__ void __launch_bounds__(128)
mlp_big_mr(float* __restrict__ x,
           const int* __restrict__ esrc,
           const int* __restrict__ edst,
           const float* __restrict__ w0, const float* __restrict__ b0,
           const float* __restrict__ w1, const float* __restrict__ b1,
           const float* __restrict__ w2, const float* __restrict__ b2,
           int s, int half_m)
{
    extern __shared__ float sm[];
    float* sA = sm;                              // 64 x ASTR_SMALL
    float* sW = sm + 64 * ASTR_SMALL;            // 2 x 64 x 128

    const int tid = threadIdx.x;
    const int cx = tid & 15, ry = tid >> 4;
    const int c0 = cx * 8;
    const int par_base = blockIdx.x * 32;

    // ---- gather 32 parent rows ----
    for (int idx = tid; idx < 32 * 32; idx += 128) {
        int r = idx >> 5, c4 = idx & 31;
        int p = par_base + r;
        if (p < half_m) {
            int node = edst[s + p];
            float4 v = reinterpret_cast<const float4*>(x + (size_t)node * Hdim)[c4];
            reinterpret_cast<float4*>(sA + r * ASTR_SMALL)[c4] = v;
        }
    }
    __syncthreads();

    // ---- layer 0: 32 rows, RPT=4 ----
    {
        ull acc4[4][4];
        zero_acc2<4>(acc4);
        const int r0p = ry * 4;
        layer_acc2<128, ASTR_SMALL, 4, 64>(sA, sW, w0, tid, r0p, c0, acc4);

        float4 bv0 = *reinterpret_cast<const float4*>(b0 + c0);
        float4 bv1 = *reinterpret_cast<const float4*>(b0 + c0 + 4);
        const float bv[8] = {bv0.x, bv0.y, bv0.z, bv0.w, bv1.x, bv1.y, bv1.z, bv1.w};
        const float* wsr = w0 + (size_t)128 * Hdim + c0;
        float4 wsa = *reinterpret_cast<const float4*>(wsr);
        float4 wsb = *reinterpret_cast<const float4*>(wsr + 4);
        const float ws[8] = {wsa.x, wsa.y, wsa.z, wsa.w, wsb.x, wsb.y, wsb.z, wsb.w};

#pragma unroll
        for (int i = 0; i < 4; ++i) {
            int p = r0p + i;
            float z[8], l[8], rr[8];
#pragma unroll
            for (int jj = 0; jj < 4; ++jj) {
                float lo, hi; UNPACK_F32X2(lo, hi, acc4[i][jj]);
                z[2 * jj]     = lo + bv[2 * jj];
                z[2 * jj + 1] = hi + bv[2 * jj + 1];
            }
#pragma unroll
            for (int j = 0; j < 8; ++j) {
                float lv = z[j];
                float rv = z[j] + ws[j];
                l[j]  = lv > 0.f ? lv : 0.f;
                rr[j] = rv > 0.f ? rv : 0.f;
            }
            *reinterpret_cast<float4*>(sA + p * ASTR_SMALL + c0) =
                make_float4(l[0], l[1], l[2], l[3]);
            *reinterpret_cast<float4*>(sA + p * ASTR_SMALL + c0 + 4) =
                make_float4(l[4], l[5], l[6], l[7]);
            *reinterpret_cast<float4*>(sA + (32 + p) * ASTR_SMALL + c0) =
                make_float4(rr[0], rr[1], rr[2], rr[3]);
            *reinterpret_cast<float4*>(sA + (32 + p) * ASTR_SMALL + c0 + 4) =
                make_float4(rr[4], rr[5], rr[6], rr[7]);
        }
    }
    __syncthreads();

    const int r0 = ry * 8;
    ull acc[8][4];

    // ---- layer 1 (64 rows) ----
    zero_acc2<8>(acc);
    layer_acc2<128, ASTR_SMALL, 8, 64>(sA, sW, w1, tid, r0, c0, acc);
    epi_bias_relu8(acc, b1, sA, r0, c0);
    __syncthreads();

    // ---- layer 2 + scatter (64 rows) ----
    zero_acc2<8>(acc);
    layer_acc2<128, ASTR_SMALL, 8, 64>(sA, sW, w2, tid, r0, c0, acc);
    {
        float4 bv0 = *reinterpret_cast<const float4*>(b2 + c0);
        float4 bv1 = *reinterpret_cast<const float4*>(b2 + c0 + 4);
        const float bv[8] = {bv0.x, bv0.y, bv0.z, bv0.w, bv1.x, bv1.y, bv1.z, bv1.w};
#pragma unroll
        for (int i = 0; i < 8; ++i) {
            int li = r0 + i;
            int lp = (li < 32) ? li : (li - 32);
            int p  = par_base + lp;
            if (p >= half_m) continue;
            int erow = (li < 32) ? p : (half_m + p);

            float v[8];
#pragma unroll
            for (int jj = 0; jj < 4; ++jj) {
                float lo, hi; UNPACK_F32X2(lo, hi, acc[i][jj]);
                v[2 * jj]     = lo + bv[2 * jj];
                v[2 * jj + 1] = hi + bv[2 * jj + 1];
            }

            int node = esrc[s + erow];
            float* pp = x + (size_t)node * Hdim + c0;
            float4 o0 = *reinterpret_cast<const float4*>(pp);
            float4 o1 = *reinterpret_cast<const float4*>(pp + 4);
            v[0] += o0.x; v[1] += o0.y; v[2] += o0.z; v[3] += o0.w;
            v[4] += o1.x; v[5] += o1.y; v[6] += o1.z; v[7] += o1.w;
            *reinterpret_cast<float4*>(pp)     = make_float4(v[0], v[1], v[2], v[3]);
            *reinterpret_cast<float4*>(pp + 4) = make_float4(v[4], v[5], v[6], v[7]);
        }
    }
}

// ======= SMALL kernel: 16-row tiles, 256 threads, cp.async double-buffered =======

template<int K, int ASTR>
__device__ __forceinline__ void layer_acc_s(const float* __restrict__ sA,
                                            float* __restrict__ sW,
                                            const float* __restrict__ w,
                                            int tid, int r0, int c0,
                                            float (&acc)[8])
{
    constexpr int WCH = 32;
    constexpr int NCH = K / WCH;
    constexpr int NF4 = WCH * 32;              // 1024 float4s per chunk
    constexpr int CHB = WCH * Hdim * 4;        // chunk bytes
    const uint32_t sWb = (uint32_t)__cvta_generic_to_shared(sW);

    {
        const float4* src = reinterpret_cast<const float4*>(w);
#pragma unroll
        for (int idx = tid; idx < NF4; idx += 256)
            cp16(sWb + (uint32_t)idx * 16, src + idx);
        asm volatile("cp.async.commit_group;" ::: "memory");
    }
    int buf = 0;
#pragma unroll 1
    for (int ch = 0; ch < NCH; ++ch) {
        if (ch + 1 < NCH) {
            const float4* src =
                reinterpret_cast<const float4*>(w + (size_t)(ch + 1) * WCH * Hdim);
            uint32_t dst = sWb + (uint32_t)(buf ^ 1) * CHB;
#pragma unroll
            for (int idx = tid; idx < NF4; idx += 256)
                cp16(dst + (uint32_t)idx * 16, src + idx);
            asm volatile("cp.async.commit_group;" ::: "memory");
            asm volatile("cp.async.wait_group 1;" ::: "memory");
        } else {
            asm volatile("cp.async.wait_group 0;" ::: "memory");
        }
        __syncthreads();

        const float* sWc = sW + buf * (WCH * Hdim);
        const int k0 = ch * WCH;
#pragma unroll 4
        for (int kq = 0; kq < WCH / 4; ++kq) {
            float4 av = *reinterpret_cast<const float4*>(sA + r0 * ASTR + k0 + kq * 4);
#pragma unroll
            for (int t = 0; t < 4; ++t) {
                const float* wr = sWc + (kq * 4 + t) * Hdim + c0;
                float4 w0v = *reinterpret_cast<const float4*>(wr);
                float4 w1v = *reinterpret_cast<const float4*>(wr + 4);
                float a = reinterpret_cast<const float*>(&av)[t];
                acc[0] = fmaf(a, w0v.x, acc[0]);
                acc[1] = fmaf(a, w0v.y, acc[1]);
                acc[2] = fmaf(a, w0v.z, acc[2]);
                acc[3] = fmaf(a, w0v.w, acc[3]);
                acc[4] = fmaf(a, w1v.x, acc[4]);
                acc[5] = fmaf(a, w1v.y, acc[5]);
                acc[6] = fmaf(a, w1v.z, acc[6]);
                acc[7] = fmaf(a, w1v.w, acc[7]);
            }
        }
        __syncthreads();
        buf ^= 1;
    }
}

template<int MODE>
__global__ void __launch_bounds__(256)
mlp_small(float* __restrict__ x,
          const float* __restrict__ ef,
          const int* __restrict__ esrc,
          const int* __restrict__ edst,
          const float* __restrict__ est,
          const float* __restrict__ w0, const float* __restrict__ b0,
          const float* __restrict__ w1, const float* __restrict__ b1,
          const float* __restrict__ w2, const float* __restrict__ b2,
          int s, int half, int nrows)
{
    extern __shared__ float sm[];
    float* sA = sm;
    float* sW = sm + 16 * ASTR_BIG;

    const int tid = threadIdx.x;
    const int cx = tid & 15, ry = tid >> 4;
    const int c0 = cx * 8, r0 = ry;
    const int row_base = blockIdx.x * 16;

    if (MODE == 0 || MODE == 1) {
        for (int idx = tid; idx < 16 * 64; idx += 256) {
            int r = idx >> 6, c4 = idx & 63;
            int row = row_base + r;
            if (row < nrows) {
                float4 v;
                if (c4 < 32) {
                    int node = esrc[s + row];
                    v = reinterpret_cast<const float4*>(x + (size_t)node * Hdim)[c4];
                } else if (MODE == 0) {
                    v = reinterpret_cast<const float4*>(ef + (size_t)(s + row) * Hdim)[c4 - 32];
                } else {
                    int node = esrc[s + half + row];
                    v = reinterpret_cast<const float4*>(x + (size_t)node * Hdim)[c4 - 32];
                }
                reinterpret_cast<float4*>(sA + r * ASTR_BIG)[c4] = v;
            }
        }
    } else {
        for (int idx = tid; idx < 16 * 32; idx += 256) {
            int r = idx >> 5, c4 = idx & 31;
            int row = row_base + r;
            if (row < nrows) {
                int node = edst[s + row];
                float4 v = reinterpret_cast<const float4*>(x + (size_t)node * Hdim)[c4];
                reinterpret_cast<float4*>(sA + r * ASTR_SMALL)[c4] = v;
            }
        }
        for (int r = tid; r < 16; r += 256) {
            int row = row_base + r;
            sA[r * ASTR_SMALL + 128] = (row < nrows) ? est[s + row] : 0.f;
        }
    }
    __syncthreads();

    float acc[8];

#pragma unroll
    for (int j = 0; j < 8; ++j) acc[j] = 0.f;
    if (MODE == 2) {
        layer_acc_s<128, ASTR_SMALL>(sA, sW, w0, tid, r0, c0, acc);
        const float* wsr = w0 + (size_t)128 * Hdim + c0;
        float stv = sA[r0 * ASTR_SMALL + 128];
#pragma unroll
        for (int j = 0; j < 8; ++j) acc[j] = fmaf(stv, wsr[j], acc[j]);
    } else {
        layer_acc_s<256, ASTR_BIG>(sA, sW, w0, tid, r0, c0, acc);
    }
    {
#pragma unroll
        for (int j = 0; j < 8; ++j) {
            float v = acc[j] + b0[c0 + j];
            acc[j] = v > 0.f ? v : 0.f;
        }
        *reinterpret_cast<float4*>(sA + r0 * ASTR_SMALL + c0) =
            make_float4(acc[0], acc[1], acc[2], acc[3]);
        *reinterpret_cast<float4*>(sA + r0 * ASTR_SMALL + c0 + 4) =
            make_float4(acc[4], acc[5], acc[6], acc[7]);
    }
    __syncthreads();

#pragma unroll
    for (int j = 0; j < 8; ++j) acc[j] = 0.f;
    layer_acc_s<128, ASTR_SMALL>(sA, sW, w1, tid, r0, c0, acc);
    {
#pragma unroll
        for (int j = 0; j < 8; ++j) {
            float v = acc[j] + b1[c0 + j];
            acc[j] = v > 0.f ? v : 0.f;
        }
        *reinterpret_cast<float4*>(sA + r0 * ASTR_SMALL + c0) =
            make_float4(acc[0], acc[1], acc[2], acc[3]);
        *reinterpret_cast<float4*>(sA + r0 * ASTR_SMALL + c0 + 4) =
            make_float4(acc[4], acc[5], acc[6], acc[7]);
    }
    __syncthreads();

#pragma unroll
    for (int j = 0; j < 8; ++j) acc[j] = 0.f;
    layer_acc_s<128, ASTR_SMALL>(sA, sW, w2, tid, r0, c0, acc);
    {
        int row = row_base + r0;
        if (row < nrows) {
#pragma unroll
            for (int j = 0; j < 8; ++j) acc[j] += b2[c0 + j];

            int node;
            if (MODE == 0)      node = edst[s + row];
            else if (MODE == 1) node = edst[s + half + row];
            else                node = esrc[s + row];

            float* p = x + (size_t)node * Hdim + c0;
            if (MODE == 2) {
                float4 o0 = *reinterpret_cast<const float4*>(p);
                float4 o1 = *reinterpret_cast<const float4*>(p + 4);
                acc[0] += o0.x; acc[1] += o0.y; acc[2] += o0.z; acc[3] += o0.w;
                acc[4] += o1.x; acc[5] += o1.y; acc[6] += o1.z; acc[7] += o1.w;
            }
            *reinterpret_cast<float4*>(p)     = make_float4(acc[0], acc[1], acc[2], acc[3]);
            *reinterpret_cast<float4*>(p + 4) = make_float4(acc[4], acc[5], acc[6], acc[7]);
        }
    }
}

// copy only leaf rows of x (everything else is provably overwritten)
__global__ void leaf_copy_kernel(float* __restrict__ x, const float* __restrict__ x_in)
{
    int idx = blockIdx.x * blockDim.x + threadIdx.x;   // over NL*32 float4s
    if (idx >= NL * 32) return;
    int r = idx >> 5, c4 = idx & 31;
    int b = r >> 13, leaf = r & (NLEAF - 1);
    size_t node = (size_t)b * NPT + leaf;
    reinterpret_cast<float4*>(x + node * Hdim)[c4] =
        reinterpret_cast<const float4*>(x_in + node * Hdim)[c4];
}

extern "C" void kernel_launch(void* const* d_in, const int* in_sizes, int n_in,
                              void* d_out, int out_size)
{
    (void)n_in; (void)out_size;

    const float* x_in = (const float*)d_in[0];
    const int*   esrc = (const int*)  d_in[1];
    const int*   edst = (const int*)  d_in[2];
    const float* est  = (const float*)d_in[3];
    const float* ef   = (const float*)d_in[4];

    int wb = (in_sizes[5] == 1) ? 6 : 5;   // input 5 = scalar gcmn_depth

    const float* nem_w0 = (const float*)d_in[wb + 0];
    const float* nem_b0 = (const float*)d_in[wb + 1];
    const float* nem_w1 = (const float*)d_in[wb + 2];
    const float* nem_b1 = (const float*)d_in[wb + 3];
    const float* nem_w2 = (const float*)d_in[wb + 4];
    const float* nem_b2 = (const float*)d_in[wb + 5];
    const float* mg_w0  = (const float*)d_in[wb + 6];
    const float* mg_b0  = (const float*)d_in[wb + 7];
    const float* mg_w1  = (const float*)d_in[wb + 8];
    const float* mg_b1  = (const float*)d_in[wb + 9];
    const float* mg_w2  = (const float*)d_in[wb + 10];
    const float* mg_b2  = (const float*)d_in[wb + 11];
    const float* mr_w0  = (const float*)d_in[wb + 12];
    const float* mr_b0  = (const float*)d_in[wb + 13];
    const float* mr_w1  = (const float*)d_in[wb + 14];
    const float* mr_b1  = (const float*)d_in[wb + 15];
    const float* mr_w2  = (const float*)d_in[wb + 16];
    const float* mr_b2  = (const float*)d_in[wb + 17];

    float* x = (float*)d_out;

    cudaFuncSetAttribute(mlp_big<0>,  cudaFuncAttributeMaxDynamicSharedMemorySize, SMEM_BIG_01);
    cudaFuncSetAttribute(mlp_big<1>,  cudaFuncAttributeMaxDynamicSharedMemorySize, SMEM_BIG_01);
    cudaFuncSetAttribute(mlp_big<2>,  cudaFuncAttributeMaxDynamicSharedMemorySize, SMEM_BIG_2);
    cudaFuncSetAttribute(mlp_big_mr,  cudaFuncAttributeMaxDynamicSharedMemorySize, SMEM_BIG_2);
    cudaFuncSetAttribute(mlp_small<1>, cudaFuncAttributeMaxDynamicSharedMemorySize, SMEM_SMALL);
    cudaFuncSetAttribute(mlp_small<2>, cudaFuncAttributeMaxDynamicSharedMemorySize, SMEM_SMALL);

    // init: only leaf rows need the original x
    leaf_copy_kernel<<<(NL * 32 + 255) / 256, 256>>>(x, x_in);

    // edge-block layout: block 0 = leaf edges (NL), block d (1..13): 8*(NLEAF>>(d-1)) edges
    int cnt[14], st[14];
    cnt[0] = NL; st[0] = 0;
    for (int d = 1; d < DEPTH; ++d) {
        cnt[d] = 8 * (NLEAF >> (d - 1));
        st[d] = st[d - 1] + cnt[d - 1];
    }

    constexpr int SMALL_THRESH = 2048;

    // ---- nem: leaf -> level-1 ----
    mlp_big<0><<<NL / 64, 128, SMEM_BIG_01>>>(
        x, ef, esrc, edst, nullptr,
        nem_w0, nem_b0, nem_w1, nem_b1, nem_w2, nem_b2, 0, 0, NL);

    // ---- mg: upward merge, levels 1..13 (sequential) ----
    for (int d = 1; d < DEPTH; ++d) {
        int half = cnt[d] / 2;
        if (half <= SMALL_THRESH)
            mlp_small<1><<<(half + 15) / 16, 256, SMEM_SMALL>>>(
                x, nullptr, esrc, edst, nullptr,
                mg_w0, mg_b0, mg_w1, mg_b1, mg_w2, mg_b2, st[d], half, half);
        else
            mlp_big<1><<<(half + 63) / 64, 128, SMEM_BIG_01>>>(
                x, nullptr, esrc, edst, nullptr,
                mg_w0, mg_b0, mg_w1, mg_b1, mg_w2, mg_b2, st[d], half, half);
    }

    // ---- mr: downward, depth 14..1 (sequential) ----
    for (int depth = DEPTH; depth >= 1; --depth) {
        if (depth == 1) {
            // leaf edges: unpaired (unique dst, state 0), full 65536 rows
            mlp_big<2><<<(NL + 63) / 64, 128, SMEM_BIG_2>>>(
                x, nullptr, esrc, edst, est,
                mr_w0, mr_b0, mr_w1, mr_b1, mr_w2, mr_b2, 0, 0, NL);
        } else {
            int b = depth - 1;
            int sE = st[b], m = cnt[b];
            if (m <= SMALL_THRESH)
                mlp_small<2><<<(m + 15) / 16, 256, SMEM_SMALL>>>(
                    x, nullptr, esrc, edst, est,
                    mr_w0, mr_b0, mr_w1, mr_b1, mr_w2, mr_b2, sE, 0, m);
            else {
                int half_m = m / 2;
                mlp_big_mr<<<(half_m + 31) / 32, 128, SMEM_BIG_2>>>(
                    x, esrc, edst,
                    mr_w0, mr_b0, mr_w1, mr_b1, mr_w2, mr_b2, sE, half_m);
            }
        }
    }
}